// round 13
// baseline (speedup 1.0000x reference)
#include <cuda_runtime.h>
#include <cuda_bf16.h>

#define INPUT_DIM 4
#define H1 64
#define H2 32
#define BATCH 64
#define SEQ 4096
#define NT 128
#define RING_G 64            // gmem ring depth in steps (power of 2)
#define CHUNK 8              // steps per flag publish / consumer chunk

typedef unsigned long long ull;

// gmem handoff state (zero-initialized at module load; consumer resets to 0 each launch)
__device__ float g_h1ring[BATCH][RING_G][H1];
__device__ int   g_prod[BATCH];   // steps published by producer
__device__ int   g_cons[BATCH];   // steps consumed (copied to smem) by consumer

// ---- packed f32x2 helpers ----
__device__ __forceinline__ ull pk2(float a, float b) {
    ull r; asm("mov.b64 %0, {%1, %2};" : "=l"(r) : "f"(a), "f"(b)); return r;
}
__device__ __forceinline__ void upk2(ull v, float& a, float& b) {
    asm("mov.b64 {%0, %1}, %2;" : "=f"(a), "=f"(b) : "l"(v));
}
__device__ __forceinline__ ull fma2(ull a, ull b, ull c) {
    ull d; asm("fma.rn.f32x2 %0, %1, %2, %3;" : "=l"(d) : "l"(a), "l"(b), "l"(c)); return d;
}
__device__ __forceinline__ ull add2(ull a, ull b) {
    ull d; asm("add.rn.f32x2 %0, %1, %2;" : "=l"(d) : "l"(a), "l"(b)); return d;
}
__device__ __forceinline__ float tanh_approx(float x) {
    float y; asm("tanh.approx.f32 %0, %1;" : "=f"(y) : "f"(x)); return y;
}
__device__ __forceinline__ int ldg_vol(const int* p) {
    int v; asm volatile("ld.volatile.global.b32 %0, [%1];" : "=r"(v) : "l"(p) : "memory"); return v;
}
__device__ __forceinline__ void stg_vol(int* p, int v) {
    asm volatile("st.volatile.global.b32 [%0], %1;" :: "l"(p), "r"(v) : "memory");
}
__device__ __forceinline__ void membar_gl() {
    asm volatile("membar.gl;" ::: "memory");
}
__device__ __forceinline__ void stg_cg_f32(float* p, float v) {
    asm volatile("st.global.cg.f32 [%0], %1;" :: "l"(p), "f"(v) : "memory");
}
__device__ __forceinline__ float4 ldg_cg_v4(const float4* p) {
    float4 v;
    asm volatile("ld.global.cg.v4.f32 {%0,%1,%2,%3}, [%4];"
                 : "=f"(v.x), "=f"(v.y), "=f"(v.z), "=f"(v.w) : "l"(p) : "memory");
    return v;
}

__global__ void __launch_bounds__(NT, 1)
lstm2_kernel(const float* __restrict__ x,
             const float* __restrict__ W_ih1, const float* __restrict__ W_hh1,
             const float* __restrict__ b_ih1, const float* __restrict__ b_hh1,
             const float* __restrict__ W_ih2, const float* __restrict__ W_hh2,
             const float* __restrict__ b_ih2, const float* __restrict__ b_hh2,
             float* __restrict__ out)
{
    const int b    = blockIdx.x >> 1;
    const int role = blockIdx.x & 1;   // 0 = L1 producer, 1 = L2 consumer
    const int tid  = threadIdx.x;

    if (role == 0) {
        // ================= Layer-1 producer CTA =================
        __shared__ __align__(16) float h1loc[2][H1];

        const int u   = tid >> 1;
        const int par = tid & 1;
        const int rowA = par * H1 + u;        // par0: i, par1: f
        const int rowB = (2 + par) * H1 + u;  // par0: g, par1: o

        const float bS = par ? 0.5f : 1.0f;   // gateB: g->tanh, o->sigmoid
        const float bA = par ? 0.5f : 1.0f;
        const float bB = par ? 0.5f : 0.0f;

        ull wA[32], wB[32], xA0, xA1, xB0, xB1;
        {
            const float2* whhA = reinterpret_cast<const float2*>(W_hh1 + rowA * H1);
            const float2* whhB = reinterpret_cast<const float2*>(W_hh1 + rowB * H1);
            #pragma unroll
            for (int k = 0; k < 32; ++k) {
                float2 v = whhA[k]; wA[k] = pk2(v.x, v.y);
                float2 w = whhB[k]; wB[k] = pk2(w.x, w.y);
            }
            const float2* wihA = reinterpret_cast<const float2*>(W_ih1 + rowA * INPUT_DIM);
            const float2* wihB = reinterpret_cast<const float2*>(W_ih1 + rowB * INPUT_DIM);
            float2 v;
            v = wihA[0]; xA0 = pk2(v.x, v.y);
            v = wihA[1]; xA1 = pk2(v.x, v.y);
            v = wihB[0]; xB0 = pk2(v.x, v.y);
            v = wihB[1]; xB1 = pk2(v.x, v.y);
        }
        const ull biasAp = pk2(b_ih1[rowA] + b_hh1[rowA], 0.0f);
        const ull biasBp = pk2(b_ih1[rowB] + b_hh1[rowB], 0.0f);

        if (par) h1loc[0][u] = 0.0f;   // h1(-1) = 0
        __syncthreads();

        float* ring = &g_h1ring[b][0][0];
        const float4* xb4 = reinterpret_cast<const float4*>(x + (size_t)b * SEQ * INPUT_DIM);
        float c = 0.0f;          // valid in par==1 lanes
        int cons = 0;
        float4 xv = __ldg(xb4);  // x(0)

        #pragma unroll 1
        for (int t = 0; t < SEQ; ++t) {
            const int tn = (t + 1 < SEQ) ? (t + 1) : t;
            const float4 xv_next = __ldg(xb4 + tn);

            // backpressure once per chunk: steps t..t+7 overwrite steps t-64..t-57
            if ((t & (CHUNK - 1)) == 0 && t >= RING_G) {
                while (cons < t - (RING_G - CHUNK)) cons = ldg_vol(&g_cons[b]);
            }

            const ulonglong2* hv = reinterpret_cast<const ulonglong2*>(h1loc[t & 1]);
            const ull xp0 = pk2(xv.x, xv.y);
            const ull xp1 = pk2(xv.z, xv.w);

            ull a0 = biasAp, a1 = 0ull, a2 = 0ull, a3 = 0ull;
            ull d0 = biasBp, d1 = 0ull, d2 = 0ull, d3 = 0ull;
            #pragma unroll
            for (int kk = 0; kk < 8; ++kk) {
                const ulonglong2 hA = hv[2 * kk];
                const ulonglong2 hB = hv[2 * kk + 1];
                a0 = fma2(wA[4 * kk + 0], hA.x, a0);
                d0 = fma2(wB[4 * kk + 0], hA.x, d0);
                a1 = fma2(wA[4 * kk + 1], hA.y, a1);
                d1 = fma2(wB[4 * kk + 1], hA.y, d1);
                a2 = fma2(wA[4 * kk + 2], hB.x, a2);
                d2 = fma2(wB[4 * kk + 2], hB.x, d2);
                a3 = fma2(wA[4 * kk + 3], hB.y, a3);
                d3 = fma2(wB[4 * kk + 3], hB.y, d3);
            }
            a0 = fma2(xA0, xp0, a0); a1 = fma2(xA1, xp1, a1);
            d0 = fma2(xB0, xp0, d0); d1 = fma2(xB1, xp1, d1);
            a0 = add2(add2(a0, a1), add2(a2, a3));
            d0 = add2(add2(d0, d1), add2(d2, d3));
            float alo, ahi, dlo, dhi;
            upk2(a0, alo, ahi); upk2(d0, dlo, dhi);
            const float rawA = alo + ahi;
            const float rawB = dlo + dhi;

            const float sA = __fmaf_rn(0.5f, tanh_approx(0.5f * rawA), 0.5f); // sigmoid
            const float sB = __fmaf_rn(bA, tanh_approx(bS * rawB), bB);

            const float val = sA * sB;                          // par0: i*g
            const float ig  = __shfl_xor_sync(0xffffffffu, val, 1);
            c = __fmaf_rn(sA, c, ig);                           // par1: c=f*c+i*g
            const float h = sB * tanh_approx(c);                // par1: h=o*tanh(c)
            if (par) {
                h1loc[(t + 1) & 1][u] = h;
                stg_cg_f32(ring + (t & (RING_G - 1)) * H1 + u, h);  // L1-bypass store
            }
            __syncthreads();
            if ((t & (CHUNK - 1)) == (CHUNK - 1) && tid == 0) {
                membar_gl();                      // cumulative: all lanes' STGs visible
                stg_vol(&g_prod[b], t + 1);       // publish chunk
            }
            xv = xv_next;
        }
    } else {
        // ================= Layer-2 consumer CTA =================
        __shared__ __align__(16) float ch[2][CHUNK][H1];   // double-buffered h1 chunks
        __shared__ __align__(16) float h2buf[2][H2];

        const int u = tid >> 2;
        const int q = tid & 3;
        const float actS = (q == 2) ? 1.0f : 0.5f;
        const float actA = (q == 2) ? 1.0f : 0.5f;
        const float actB = (q == 2) ? 0.0f : 0.5f;

        const int g = q * H2 + u;
        ull w2[48];
        {
            const float2* wih = reinterpret_cast<const float2*>(W_ih2 + g * H1);
            #pragma unroll
            for (int k = 0; k < 32; ++k) { const float2 v = wih[k]; w2[k] = pk2(v.x, v.y); }
            const float2* whh = reinterpret_cast<const float2*>(W_hh2 + g * H2);
            #pragma unroll
            for (int k = 0; k < 16; ++k) { const float2 v = whh[k]; w2[32 + k] = pk2(v.x, v.y); }
        }
        const ull biasp = pk2(b_ih2[g] + b_hh2[g], 0.0f);
        float* outb = out + (size_t)b * SEQ * H2;
        const float* ring = &g_h1ring[b][0][0];

        if ((tid & 3) == 0) h2buf[0][tid >> 2] = 0.0f;   // h2(-1)=0
        __syncthreads();

        float c = 0.0f;
        int prod_seen = 0;

        #pragma unroll 1
        for (int k = 0; k < SEQ / CHUNK; ++k) {
            const int need = CHUNK * k + CHUNK;
            if (prod_seen < need) {
                do { prod_seen = ldg_vol(&g_prod[b]); } while (prod_seen < need);
            }
            membar_gl();   // acquire: order flag read before data reads

            // copy chunk gmem -> smem (L1-bypassing loads; ring slots are reused)
            {
                const float4* src = reinterpret_cast<const float4*>(
                    ring + ((CHUNK * k) & (RING_G - 1)) * H1) + tid;
                reinterpret_cast<float4*>(&ch[k & 1][0][0])[tid] = ldg_cg_v4(src);
            }
            __syncthreads();
            if (tid == 0) {
                membar_gl();                       // loads done before releasing slots
                stg_vol(&g_cons[b], CHUNK * k + CHUNK);
            }

            #pragma unroll 1
            for (int s = 0; s < CHUNK; ++s) {
                const int t = CHUNK * k + s;
                const ulonglong2* hv = reinterpret_cast<const ulonglong2*>(ch[k & 1][s]);
                const ulonglong2* gv = reinterpret_cast<const ulonglong2*>(h2buf[t & 1]);

                ull a0 = biasp, a1 = 0ull, a2 = 0ull, a3 = 0ull;
                #pragma unroll
                for (int kk = 0; kk < 8; ++kk) {
                    const ulonglong2 hA = hv[2 * kk];
                    const ulonglong2 hB = hv[2 * kk + 1];
                    a0 = fma2(w2[4 * kk + 0], hA.x, a0);
                    a1 = fma2(w2[4 * kk + 1], hA.y, a1);
                    a2 = fma2(w2[4 * kk + 2], hB.x, a2);
                    a3 = fma2(w2[4 * kk + 3], hB.y, a3);
                }
                #pragma unroll
                for (int kk = 0; kk < 4; ++kk) {
                    const ulonglong2 hA = gv[2 * kk];
                    const ulonglong2 hB = gv[2 * kk + 1];
                    a0 = fma2(w2[32 + 4 * kk + 0], hA.x, a0);
                    a1 = fma2(w2[32 + 4 * kk + 1], hA.y, a1);
                    a2 = fma2(w2[32 + 4 * kk + 2], hB.x, a2);
                    a3 = fma2(w2[32 + 4 * kk + 3], hB.y, a3);
                }
                a0 = add2(add2(a0, a1), add2(a2, a3));
                float lo, hi; upk2(a0, lo, hi);
                const float raw = lo + hi;

                const float act = __fmaf_rn(actA, tanh_approx(actS * raw), actB);
                const float v1 = __shfl_xor_sync(0xffffffffu, act, 1);
                const float v2 = __shfl_xor_sync(0xffffffffu, act, 2);
                const float v3 = __shfl_xor_sync(0xffffffffu, act, 3);
                c = __fmaf_rn(v1, c, act * v2);
                const float h = v3 * tanh_approx(c);

                if (q == 0) {
                    h2buf[(t + 1) & 1][u] = h;
                    outb[(size_t)t * H2 + u] = h;
                }
                __syncthreads();
            }
        }

        // reset handoff state for the next (stream-serialized) launch
        __syncthreads();
        if (tid == 0) { stg_vol(&g_prod[b], 0); stg_vol(&g_cons[b], 0); }
    }
}

extern "C" void kernel_launch(void* const* d_in, const int* in_sizes, int n_in,
                              void* d_out, int out_size) {
    const float* x     = (const float*)d_in[0];
    const float* W_ih1 = (const float*)d_in[1];
    const float* W_hh1 = (const float*)d_in[2];
    const float* b_ih1 = (const float*)d_in[3];
    const float* b_hh1 = (const float*)d_in[4];
    const float* W_ih2 = (const float*)d_in[5];
    const float* W_hh2 = (const float*)d_in[6];
    const float* b_ih2 = (const float*)d_in[7];
    const float* b_hh2 = (const float*)d_in[8];
    float* out = (float*)d_out;

    lstm2_kernel<<<2 * BATCH, NT>>>(x, W_ih1, W_hh1, b_ih1, b_hh1,
                                    W_ih2, W_hh2, b_ih2, b_hh2, out);
}